// round 15
// baseline (speedup 1.0000x reference)
#include <cuda_runtime.h>
#include <cuda_fp16.h>
#include <math.h>
#include <stdint.h>

// Problem constants
#define BATCH 2
#define T_LEN 2048
#define D_MODEL 2048
#define NH 16
#define NKV 4
#define HD 128
#define EPS 1e-6f
#define M_ROWS (BATCH * T_LEN)  // 4096

// ---------------- scratch (device globals; no allocation allowed) ----------
__device__ __half g_xh[M_ROWS * D_MODEL];
__device__ __half g_ah[M_ROWS * D_MODEL];
__device__ __half g_wq[D_MODEL * D_MODEL];      // [N,K] transposed
__device__ __half g_wk[NKV * HD * D_MODEL];
__device__ __half g_wv[NKV * HD * D_MODEL];
__device__ __half g_wo[D_MODEL * D_MODEL];

__device__ __half g_qh[M_ROWS * NH * HD];
__device__ __half g_kh[M_ROWS * NKV * HD];
__device__ __half g_vh[M_ROWS * NKV * HD];

// ---------------- helpers -----------------------------------------------------
__device__ __forceinline__ uint32_t smem_u32(const void* p) {
    uint32_t a;
    asm("{ .reg .u64 t; cvta.to.shared.u64 t, %1; cvt.u32.u64 %0, t; }"
        : "=r"(a) : "l"(p));
    return a;
}

#define CP16(dst, src) \
    asm volatile("cp.async.cg.shared.global [%0], [%1], 16;" :: "r"(dst), "l"(src))
#define CP_COMMIT() asm volatile("cp.async.commit_group;" ::: "memory")
#define CP_WAIT(n)  asm volatile("cp.async.wait_group %0;" :: "n"(n) : "memory")

#define LDSM_X4(r0, r1, r2, r3, addr) \
    asm volatile("ldmatrix.sync.aligned.m8n8.x4.shared.b16 {%0,%1,%2,%3}, [%4];" \
                 : "=r"(r0), "=r"(r1), "=r"(r2), "=r"(r3) : "r"(addr))
#define LDSM_X4_T(r0, r1, r2, r3, addr) \
    asm volatile("ldmatrix.sync.aligned.m8n8.x4.trans.shared.b16 {%0,%1,%2,%3}, [%4];" \
                 : "=r"(r0), "=r"(r1), "=r"(r2), "=r"(r3) : "r"(addr))

// fp16 inputs, fp32 accumulator
__device__ __forceinline__ void mma_h(float* c, const uint32_t* a, uint32_t b0, uint32_t b1) {
    asm volatile(
        "mma.sync.aligned.m16n8k16.row.col.f32.f16.f16.f32 "
        "{%0,%1,%2,%3}, {%4,%5,%6,%7}, {%8,%9}, {%0,%1,%2,%3};"
        : "+f"(c[0]), "+f"(c[1]), "+f"(c[2]), "+f"(c[3])
        : "r"(a[0]), "r"(a[1]), "r"(a[2]), "r"(a[3]), "r"(b0), "r"(b1));
}

__device__ __forceinline__ uint32_t pack_h2(float x, float y) {
    __half2 h = __floats2half2_rn(x, y);
    return *reinterpret_cast<uint32_t*>(&h);
}

// ---------------- merged prep kernel: x cvt + 4 weight transposes -------------
__global__ __launch_bounds__(256) void prep(
    const float* __restrict__ x,
    const float* __restrict__ Wq, const float* __restrict__ Wk,
    const float* __restrict__ Wv, const float* __restrict__ Wo,
    __half* __restrict__ xh, __half* __restrict__ wq, __half* __restrict__ wk,
    __half* __restrict__ wv, __half* __restrict__ wo)
{
    __shared__ float tile[32][33];
    int bx = blockIdx.x;
    if (bx < 8192) {
        int i = bx * 256 + threadIdx.x;
        float4 v = ((const float4*)x)[i];
        ((uint2*)xh)[i] = make_uint2(pack_h2(v.x, v.y), pack_h2(v.z, v.w));
        return;
    }
    bx -= 8192;
    const float* W;
    __half* T;
    int N, t;
    if (bx < 4096)      { W = Wq; T = wq; N = 2048; t = bx; }
    else if (bx < 5120) { W = Wk; T = wk; N = 512;  t = bx - 4096; }
    else if (bx < 6144) { W = Wv; T = wv; N = 512;  t = bx - 5120; }
    else                { W = Wo; T = wo; N = 2048; t = bx - 6144; }
    const int K = 2048;
    const int ntn = N >> 5;
    const int n0 = (t % ntn) * 32, k0 = (t / ntn) * 32;
    const int tx = threadIdx.x & 31, ty4 = (threadIdx.x >> 5) * 4;
#pragma unroll
    for (int i = 0; i < 4; i++)
        tile[ty4 + i][tx] = W[(size_t)(k0 + ty4 + i) * N + n0 + tx];
    __syncthreads();
#pragma unroll
    for (int i = 0; i < 4; i++)
        T[(size_t)(n0 + ty4 + i) * K + k0 + tx] = __float2half_rn(tile[tx][ty4 + i]);
}

// ---------------- FP16 HMMA GEMM, 128x128 tile, BK=64, 3-stage cp.async -------
// C[M,N] = A[M,K] @ Bt[N,K]^T. 256 threads (warps 4x2), warp tile 32x64.
// Epilogue modes: 0 = fp32 store, 1 = fp16 store, 2 = RMSNorm+RoPE -> fp16
#define G_STAGE 32768
#define GEMM_SMEM (3 * G_STAGE + 1024)
#define SWZG(r, c) ((uint32_t)((r) * 128 + (((c) ^ ((r) & 7)) << 4)))

__global__ __launch_bounds__(256, 2) void mma_gemm(
    const __half* __restrict__ Ahp,
    const __half* __restrict__ B0, const __half* __restrict__ B1,
    const __half* __restrict__ B2,
    void* __restrict__ O0, void* __restrict__ O1, void* __restrict__ O2,
    int mode0, int mode1, int mode2,
    const float* __restrict__ sv0, const float* __restrict__ sv1,
    const float* __restrict__ cosT, const float* __restrict__ sinT,
    float ps0, float ps1,
    int K, int n0, int n1, int N0, int N1, int N2)
{
    extern __shared__ char smem[];
    const uint32_t sbase = smem_u32(smem);

    const int tid = threadIdx.x;
    const int lane = tid & 31, wid = tid >> 5;
    const int wm = wid >> 1, wn = wid & 1;
    const int bx = blockIdx.x;
    int mode, bn, N;
    const __half* B;
    void* O;
    const float* scaleV;
    float prescale;
    if (bx < n0) {
        mode = mode0; bn = bx * 128; B = B0; N = N0; O = O0;
        scaleV = sv0; prescale = ps0;
    } else if (bx < n0 + n1) {
        mode = mode1; bn = (bx - n0) * 128; B = B1; N = N1; O = O1;
        scaleV = sv1; prescale = ps1;
    } else {
        mode = mode2; bn = (bx - n0 - n1) * 128; B = B2; N = N2; O = O2;
        scaleV = sv0; prescale = 1.f;
    }
    const int bm = blockIdx.y * 128;
    const int NT = K / 64;

    float acc[2][8][4];
#pragma unroll
    for (int i = 0; i < 2; i++)
#pragma unroll
        for (int j = 0; j < 8; j++)
#pragma unroll
            for (int l = 0; l < 4; l++) acc[i][j][l] = 0.f;

    auto issue = [&](int it) {
        const int k0 = it * 64;
        const uint32_t sb = sbase + (it % 3) * G_STAGE;
#pragma unroll
        for (int i = 0; i < 8; i++) {
            int id = i * 256 + tid;          // 0..2047
            int r = (id >> 3) & 127, c = id & 7;
            if (id < 1024) {                 // A: 128 rows x 8 chunks
                CP16(sb + SWZG(r, c), Ahp + (size_t)(bm + r) * K + k0 + c * 8);
            } else {                         // B: 128 rows x 8 chunks
                CP16(sb + 16384 + SWZG(r, c), B + (size_t)(bn + r) * K + k0 + c * 8);
            }
        }
    };

    issue(0); CP_COMMIT();
    issue(1); CP_COMMIT();

    const int lrow = lane & 15, lc = lane >> 4;

    for (int it = 0; it < NT; ++it) {
        if (it + 1 < NT) { CP_WAIT(1); } else { CP_WAIT(0); }
        __syncthreads();
        if (it + 2 < NT) { issue(it + 2); CP_COMMIT(); }

        const uint32_t sb = sbase + (it % 3) * G_STAGE;
#pragma unroll
        for (int ks = 0; ks < 4; ks++) {
            const int c = ks * 2 + lc;
            uint32_t ah[2][4];
#pragma unroll
            for (int mt = 0; mt < 2; mt++) {
                int r = wm * 32 + mt * 16 + lrow;
                LDSM_X4(ah[mt][0], ah[mt][1], ah[mt][2], ah[mt][3], sb + SWZG(r, c));
            }
#pragma unroll
            for (int j = 0; j < 4; j++) {
                int r = wn * 64 + 16 * j + lrow;
                uint32_t b4[4];
                LDSM_X4(b4[0], b4[1], b4[2], b4[3], sb + 16384 + SWZG(r, c));
#pragma unroll
                for (int half = 0; half < 2; half++) {
                    int nt = 2 * j + half;
#pragma unroll
                    for (int mt = 0; mt < 2; mt++)
                        mma_h(acc[mt][nt], ah[mt], b4[half], b4[half + 2]);
                }
            }
        }
        // no bottom barrier: 3-stage rotation + next top barrier order reuse
    }

    // ---- epilogue ----
    const int g = lane >> 2, q = lane & 3;
    if (mode == 0) {
        float* Cf = (float*)O;
#pragma unroll
        for (int mt = 0; mt < 2; mt++)
#pragma unroll
            for (int nt = 0; nt < 8; nt++) {
                int row = bm + wm * 32 + mt * 16 + g;
                int col = bn + wn * 64 + nt * 8 + 2 * q;
                *(float2*)&Cf[(size_t)row * N + col] =
                    make_float2(acc[mt][nt][0], acc[mt][nt][1]);
                *(float2*)&Cf[(size_t)(row + 8) * N + col] =
                    make_float2(acc[mt][nt][2], acc[mt][nt][3]);
            }
    } else if (mode == 1) {
        uint32_t* Ch = (uint32_t*)O;
#pragma unroll
        for (int mt = 0; mt < 2; mt++)
#pragma unroll
            for (int nt = 0; nt < 8; nt++) {
                int row = bm + wm * 32 + mt * 16 + g;
                int col = bn + wn * 64 + nt * 8 + 2 * q;
                Ch[((size_t)row * N + col) >> 1] =
                    pack_h2(acc[mt][nt][0], acc[mt][nt][1]);
                Ch[((size_t)(row + 8) * N + col) >> 1] =
                    pack_h2(acc[mt][nt][2], acc[mt][nt][3]);
            }
    } else {
        // fused RMSNorm (this block's 128 cols = one head) + RoPE -> fp16
        float* red = (float*)(smem + 3 * G_STAGE);  // [2 wn][128 rows]
        __syncthreads();
#pragma unroll
        for (int mt = 0; mt < 2; mt++) {
            float s0 = 0.f, s1 = 0.f;
#pragma unroll
            for (int nt = 0; nt < 8; nt++) {
                s0 += acc[mt][nt][0] * acc[mt][nt][0] + acc[mt][nt][1] * acc[mt][nt][1];
                s1 += acc[mt][nt][2] * acc[mt][nt][2] + acc[mt][nt][3] * acc[mt][nt][3];
            }
            s0 += __shfl_xor_sync(0xffffffffu, s0, 1);
            s0 += __shfl_xor_sync(0xffffffffu, s0, 2);
            s1 += __shfl_xor_sync(0xffffffffu, s1, 1);
            s1 += __shfl_xor_sync(0xffffffffu, s1, 2);
            if (q == 0) {
                red[wn * 128 + wm * 32 + mt * 16 + g] = s0;
                red[wn * 128 + wm * 32 + mt * 16 + g + 8] = s1;
            }
        }
        __syncthreads();
        uint32_t* Ch = (uint32_t*)O;
#pragma unroll
        for (int mt = 0; mt < 2; mt++) {
#pragma unroll
            for (int rr = 0; rr < 2; rr++) {
                int r = wm * 32 + mt * 16 + g + rr * 8;
                float rinv = rsqrtf((red[r] + red[128 + r]) * (1.0f / HD) + EPS);
                int t = (bm + r) & (T_LEN - 1);
#pragma unroll
                for (int nt = 0; nt < 8; nt++) {
                    int d = wn * 64 + nt * 8 + 2 * q;
                    float2 sc = *(const float2*)&scaleV[d];
                    float2 cs = *(const float2*)&cosT[t * HD + d];
                    float2 sn = *(const float2*)&sinT[t * HD + d];
                    float v0 = acc[mt][nt][rr * 2 + 0] * rinv * sc.x;
                    float v1 = acc[mt][nt][rr * 2 + 1] * rinv * sc.y;
                    float o0 = (v0 * cs.x - v1 * sn.x) * prescale;
                    float o1 = (v1 * cs.y + v0 * sn.y) * prescale;
                    Ch[(((size_t)(bm + r)) * N + bn + d) >> 1] = pack_h2(o0, o1);
                }
            }
        }
    }
}

// ---------------- FP16 HMMA causal GQA flash attention ------------------------
// BQ=128 (8 warps x m16), BK=64, HD=128. Q in smem (32KB) + 2-stage K/V
// (2 x 32KB) = 96KB -> 2 CTAs/SM (16 warps/SM). 256 threads, <=128 regs.
#define FA_KV_STAGE 32768
#define FA_SMEM (32768 + 2 * FA_KV_STAGE)
#define SWZ256(r, c) ((uint32_t)((r) * 256 + (((c) ^ ((r) & 7)) << 4)))

__global__ __launch_bounds__(256, 2) void flash_mma(
    const __half* __restrict__ qh, const __half* __restrict__ kh,
    const __half* __restrict__ vh, __half* __restrict__ ohp)
{
    extern __shared__ char fsm[];
    const uint32_t sb = smem_u32(fsm);
    const uint32_t Qh_s = sb;
    const uint32_t ST = sb + 32768;  // per stage: Kh(16K) Vh(16K)

    const int qb = (int)gridDim.x - 1 - (int)blockIdx.x;  // heavy tiles first
    const int h = blockIdx.y, b = blockIdx.z;
    const int kvh = h >> 2;
    const int tid = threadIdx.x;
    const int lane = tid & 31, wid = tid >> 5;   // wid 0..7
    const int g = lane >> 2, qq = lane & 3;
    const int q0 = qb * 128;
    const int q0w = q0 + wid * 16;
    const int nkv = 2 * qb + 2;

    // ---- load Q (128 rows x 16 chunks = 2048) ----
#pragma unroll
    for (int i = 0; i < 8; i++) {
        int id = i * 256 + tid;
        int c = id & 15, r = id >> 4;
        CP16(Qh_s + SWZ256(r, c),
             qh + ((size_t)(b * T_LEN + q0 + r) * NH + h) * HD + c * 8);
    }
    CP_COMMIT();

    auto issue_kv = [&](int kt) {
        const int kv0 = kt * 64;
        const uint32_t sbs = ST + (kt & 1) * FA_KV_STAGE;
#pragma unroll
        for (int i = 0; i < 8; i++) {
            int id = i * 256 + tid;
            int c = id & 15, r = (id >> 4) & 63, arr = id >> 10;  // k, v
            const __half* src = arr ? vh : kh;
            uint32_t dst = sbs + arr * 16384 + SWZ256(r, c);
            CP16(dst, src + ((size_t)(b * T_LEN + kv0 + r) * NKV + kvh) * HD + c * 8);
        }
    };

    issue_kv(0);
    CP_COMMIT();

    float m0 = -1e30f, m1 = -1e30f, l0 = 0.f, l1 = 0.f;
    float Oacc[16][4];
#pragma unroll
    for (int nt = 0; nt < 16; nt++)
#pragma unroll
        for (int e = 0; e < 4; e++) Oacc[nt][e] = 0.f;

    const int lrow = lane & 15, lc = lane >> 4;

    for (int kt = 0; kt < nkv; kt++) {
        if (kt + 1 < nkv) {
            issue_kv(kt + 1);
            CP_COMMIT();
            CP_WAIT(1);
        } else {
            CP_WAIT(0);
        }
        __syncthreads();

        const int kv0 = kt * 64;
        const uint32_t sbs = ST + (kt & 1) * FA_KV_STAGE;

        if (kv0 <= q0w + 15) {  // skip fully-masked tiles for this warp
            float S[8][4];
#pragma unroll
            for (int nt = 0; nt < 8; nt++)
#pragma unroll
                for (int e = 0; e < 4; e++) S[nt][e] = 0.f;

#pragma unroll
            for (int ks = 0; ks < 8; ks++) {
                const int c = ks * 2 + lc;
                int qr = wid * 16 + lrow;
                uint32_t aq[4];
                LDSM_X4(aq[0], aq[1], aq[2], aq[3], Qh_s + SWZ256(qr, c));
#pragma unroll
                for (int j = 0; j < 4; j++) {
                    int r = 16 * j + lrow;
                    uint32_t b4[4];
                    LDSM_X4(b4[0], b4[1], b4[2], b4[3], sbs + SWZ256(r, c));
#pragma unroll
                    for (int half = 0; half < 2; half++)
                        mma_h(S[2 * j + half], aq, b4[half], b4[half + 2]);
                }
            }

            if (kv0 + 63 > q0w) {  // diagonal region: mask
#pragma unroll
                for (int nt = 0; nt < 8; nt++) {
                    int col = kv0 + nt * 8 + qq * 2;
                    int r0 = q0w + g, r1 = q0w + g + 8;
                    if (col > r0) S[nt][0] = -1e30f;
                    if (col + 1 > r0) S[nt][1] = -1e30f;
                    if (col > r1) S[nt][2] = -1e30f;
                    if (col + 1 > r1) S[nt][3] = -1e30f;
                }
            }

            float mx0 = -1e30f, mx1 = -1e30f;
#pragma unroll
            for (int nt = 0; nt < 8; nt++) {
                mx0 = fmaxf(mx0, fmaxf(S[nt][0], S[nt][1]));
                mx1 = fmaxf(mx1, fmaxf(S[nt][2], S[nt][3]));
            }
            mx0 = fmaxf(mx0, __shfl_xor_sync(0xffffffffu, mx0, 1));
            mx0 = fmaxf(mx0, __shfl_xor_sync(0xffffffffu, mx0, 2));
            mx1 = fmaxf(mx1, __shfl_xor_sync(0xffffffffu, mx1, 1));
            mx1 = fmaxf(mx1, __shfl_xor_sync(0xffffffffu, mx1, 2));
            float mn0 = fmaxf(m0, mx0), mn1 = fmaxf(m1, mx1);
            float al0 = exp2f(m0 - mn0), al1 = exp2f(m1 - mn1);
            m0 = mn0; m1 = mn1;
            float sum0 = 0.f, sum1 = 0.f;
#pragma unroll
            for (int nt = 0; nt < 8; nt++) {
                S[nt][0] = exp2f(S[nt][0] - mn0);
                S[nt][1] = exp2f(S[nt][1] - mn0);
                S[nt][2] = exp2f(S[nt][2] - mn1);
                S[nt][3] = exp2f(S[nt][3] - mn1);
                sum0 += S[nt][0] + S[nt][1];
                sum1 += S[nt][2] + S[nt][3];
            }
            sum0 += __shfl_xor_sync(0xffffffffu, sum0, 1);
            sum0 += __shfl_xor_sync(0xffffffffu, sum0, 2);
            sum1 += __shfl_xor_sync(0xffffffffu, sum1, 1);
            sum1 += __shfl_xor_sync(0xffffffffu, sum1, 2);
            l0 = l0 * al0 + sum0;
            l1 = l1 * al1 + sum1;
#pragma unroll
            for (int nt = 0; nt < 16; nt++) {
                Oacc[nt][0] *= al0; Oacc[nt][1] *= al0;
                Oacc[nt][2] *= al1; Oacc[nt][3] *= al1;
            }

            uint32_t Ph[4][4];
#pragma unroll
            for (int ktp = 0; ktp < 4; ktp++) {
                Ph[ktp][0] = pack_h2(S[2 * ktp][0], S[2 * ktp][1]);
                Ph[ktp][1] = pack_h2(S[2 * ktp][2], S[2 * ktp][3]);
                Ph[ktp][2] = pack_h2(S[2 * ktp + 1][0], S[2 * ktp + 1][1]);
                Ph[ktp][3] = pack_h2(S[2 * ktp + 1][2], S[2 * ktp + 1][3]);
            }

#pragma unroll
            for (int ktp = 0; ktp < 4; ktp++) {
#pragma unroll
                for (int j = 0; j < 8; j++) {
                    int r = ktp * 16 + lrow;
                    int c = 2 * j + lc;
                    uint32_t v0, v1, v2, v3;
                    LDSM_X4_T(v0, v1, v2, v3, sbs + 16384 + SWZ256(r, c));
                    mma_h(Oacc[2 * j], Ph[ktp], v0, v1);
                    mma_h(Oacc[2 * j + 1], Ph[ktp], v2, v3);
                }
            }
        }
        __syncthreads();  // protect stage reuse (2-stage ring)
    }

    // ---- write O as fp16 (att layout [b*T, NH*HD]) ----
    float inv0 = 1.f / l0, inv1 = 1.f / l1;
    const size_t base0 = (size_t)(b * T_LEN + q0w + g) * (NH * HD) + h * HD;
    const size_t base1 = base0 + (size_t)8 * NH * HD;
#pragma unroll
    for (int nt = 0; nt < 16; nt++) {
        int col = nt * 8 + qq * 2;
        ((uint32_t*)ohp)[(base0 + col) >> 1] =
            pack_h2(Oacc[nt][0] * inv0, Oacc[nt][1] * inv0);
        ((uint32_t*)ohp)[(base1 + col) >> 1] =
            pack_h2(Oacc[nt][2] * inv1, Oacc[nt][3] * inv1);
    }
}

// ---------------- launcher ---------------------------------------------------
extern "C" void kernel_launch(void* const* d_in, const int* in_sizes, int n_in,
                              void* d_out, int out_size)
{
    const float* x       = (const float*)d_in[0];
    const float* Wq      = (const float*)d_in[1];
    const float* Wk      = (const float*)d_in[2];
    const float* Wv      = (const float*)d_in[3];
    const float* Wo      = (const float*)d_in[4];
    const float* q_scale = (const float*)d_in[5];
    const float* k_scale = (const float*)d_in[6];
    const float* cosT    = (const float*)d_in[7];
    const float* sinT    = (const float*)d_in[8];
    float* out = (float*)d_out;

    __half *xh, *ah, *wq, *wk, *wv, *wo, *qh, *kh, *vh;
    cudaGetSymbolAddress((void**)&xh, g_xh);
    cudaGetSymbolAddress((void**)&ah, g_ah);
    cudaGetSymbolAddress((void**)&wq, g_wq);  cudaGetSymbolAddress((void**)&wk, g_wk);
    cudaGetSymbolAddress((void**)&wv, g_wv);  cudaGetSymbolAddress((void**)&wo, g_wo);
    cudaGetSymbolAddress((void**)&qh, g_qh);
    cudaGetSymbolAddress((void**)&kh, g_kh);  cudaGetSymbolAddress((void**)&vh, g_vh);

    static bool attr_set = false;
    if (!attr_set) {
        cudaFuncSetAttribute(mma_gemm, cudaFuncAttributeMaxDynamicSharedMemorySize, GEMM_SMEM);
        cudaFuncSetAttribute(flash_mma, cudaFuncAttributeMaxDynamicSharedMemorySize, FA_SMEM);
        attr_set = true;
    }

    const int M = M_ROWS;  // 4096
    const float qk_scale = 1.4426950408889634f * 0.08838834764831845f;  // log2e/sqrt(HD)

    // one merged conversion launch
    prep<<<18432, 256>>>(x, Wq, Wk, Wv, Wo, xh, wq, wk, wv, wo);

    // merged Q+K+V projections with fused RMSNorm+RoPE epilogues
    mma_gemm<<<dim3(24, M / 128), 256, GEMM_SMEM>>>(
        xh, wq, wk, wv, qh, kh, vh,
        2, 2, 1,
        q_scale, k_scale, cosT, sinT,
        qk_scale, 1.0f,
        D_MODEL, 16, 4, NH * HD, NKV * HD, NKV * HD);

    // flash attention -> fp16 (BQ=128, 8 warps, 96KB, 2 CTAs/SM)
    flash_mma<<<dim3(T_LEN / 128, NH, BATCH), 256, FA_SMEM>>>(qh, kh, vh, ah);

    // output projection (fp32 out)
    mma_gemm<<<dim3(16, M / 128), 256, GEMM_SMEM>>>(
        ah, wo, nullptr, nullptr, out, nullptr, nullptr,
        0, 0, 0,
        nullptr, nullptr, nullptr, nullptr,
        1.0f, 1.0f,
        D_MODEL, 16, 0, D_MODEL, 0, 0);
}

// round 16
// speedup vs baseline: 1.1275x; 1.1275x over previous
#include <cuda_runtime.h>
#include <cuda_fp16.h>
#include <math.h>
#include <stdint.h>

// Problem constants
#define BATCH 2
#define T_LEN 2048
#define D_MODEL 2048
#define NH 16
#define NKV 4
#define HD 128
#define EPS 1e-6f
#define M_ROWS (BATCH * T_LEN)  // 4096

// ---------------- scratch (device globals; no allocation allowed) ----------
__device__ __half g_xh[M_ROWS * D_MODEL];
__device__ __half g_ah[M_ROWS * D_MODEL];
__device__ __half g_wq[D_MODEL * D_MODEL];      // [N,K] transposed
__device__ __half g_wk[NKV * HD * D_MODEL];
__device__ __half g_wv[NKV * HD * D_MODEL];
__device__ __half g_wo[D_MODEL * D_MODEL];

__device__ __half g_qh[M_ROWS * NH * HD];
__device__ __half g_kh[M_ROWS * NKV * HD];
__device__ __half g_vh[M_ROWS * NKV * HD];

// ---------------- helpers -----------------------------------------------------
__device__ __forceinline__ uint32_t smem_u32(const void* p) {
    uint32_t a;
    asm("{ .reg .u64 t; cvta.to.shared.u64 t, %1; cvt.u32.u64 %0, t; }"
        : "=r"(a) : "l"(p));
    return a;
}

#define CP16(dst, src) \
    asm volatile("cp.async.cg.shared.global [%0], [%1], 16;" :: "r"(dst), "l"(src))
#define CP_COMMIT() asm volatile("cp.async.commit_group;" ::: "memory")
#define CP_WAIT(n)  asm volatile("cp.async.wait_group %0;" :: "n"(n) : "memory")

#define LDSM_X4(r0, r1, r2, r3, addr) \
    asm volatile("ldmatrix.sync.aligned.m8n8.x4.shared.b16 {%0,%1,%2,%3}, [%4];" \
                 : "=r"(r0), "=r"(r1), "=r"(r2), "=r"(r3) : "r"(addr))
#define LDSM_X4_T(r0, r1, r2, r3, addr) \
    asm volatile("ldmatrix.sync.aligned.m8n8.x4.trans.shared.b16 {%0,%1,%2,%3}, [%4];" \
                 : "=r"(r0), "=r"(r1), "=r"(r2), "=r"(r3) : "r"(addr))

// fp16 inputs, fp32 accumulator
__device__ __forceinline__ void mma_h(float* c, const uint32_t* a, uint32_t b0, uint32_t b1) {
    asm volatile(
        "mma.sync.aligned.m16n8k16.row.col.f32.f16.f16.f32 "
        "{%0,%1,%2,%3}, {%4,%5,%6,%7}, {%8,%9}, {%0,%1,%2,%3};"
        : "+f"(c[0]), "+f"(c[1]), "+f"(c[2]), "+f"(c[3])
        : "r"(a[0]), "r"(a[1]), "r"(a[2]), "r"(a[3]), "r"(b0), "r"(b1));
}

__device__ __forceinline__ uint32_t pack_h2(float x, float y) {
    __half2 h = __floats2half2_rn(x, y);
    return *reinterpret_cast<uint32_t*>(&h);
}

// ---------------- merged prep kernel: x cvt + 4 weight transposes -------------
__global__ __launch_bounds__(256) void prep(
    const float* __restrict__ x,
    const float* __restrict__ Wq, const float* __restrict__ Wk,
    const float* __restrict__ Wv, const float* __restrict__ Wo,
    __half* __restrict__ xh, __half* __restrict__ wq, __half* __restrict__ wk,
    __half* __restrict__ wv, __half* __restrict__ wo)
{
    __shared__ float tile[32][33];
    int bx = blockIdx.x;
    if (bx < 8192) {
        int i = bx * 256 + threadIdx.x;
        float4 v = ((const float4*)x)[i];
        ((uint2*)xh)[i] = make_uint2(pack_h2(v.x, v.y), pack_h2(v.z, v.w));
        return;
    }
    bx -= 8192;
    const float* W;
    __half* T;
    int N, t;
    if (bx < 4096)      { W = Wq; T = wq; N = 2048; t = bx; }
    else if (bx < 5120) { W = Wk; T = wk; N = 512;  t = bx - 4096; }
    else if (bx < 6144) { W = Wv; T = wv; N = 512;  t = bx - 5120; }
    else                { W = Wo; T = wo; N = 2048; t = bx - 6144; }
    const int K = 2048;
    const int ntn = N >> 5;
    const int n0 = (t % ntn) * 32, k0 = (t / ntn) * 32;
    const int tx = threadIdx.x & 31, ty4 = (threadIdx.x >> 5) * 4;
#pragma unroll
    for (int i = 0; i < 4; i++)
        tile[ty4 + i][tx] = W[(size_t)(k0 + ty4 + i) * N + n0 + tx];
    __syncthreads();
#pragma unroll
    for (int i = 0; i < 4; i++)
        T[(size_t)(n0 + ty4 + i) * K + k0 + tx] = __float2half_rn(tile[tx][ty4 + i]);
}

// ---------------- FP16 HMMA GEMM, 64x128 tile, BK=64, 3-stage cp.async --------
// C[M,N] = A[M,K] @ Bt[N,K]^T. 128 threads (warps 2x2), warp tile 32x64.
// 72KB smem -> 3 CTAs/SM (better wave quantization + 12 warps/SM).
// Epilogue modes: 0 = fp32 store, 1 = fp16 store, 2 = RMSNorm+RoPE -> fp16
#define G_STAGE 24576
#define GEMM_SMEM (3 * G_STAGE + 1024)
#define SWZG(r, c) ((uint32_t)((r) * 128 + (((c) ^ ((r) & 7)) << 4)))

__global__ __launch_bounds__(128, 3) void mma_gemm(
    const __half* __restrict__ Ahp,
    const __half* __restrict__ B0, const __half* __restrict__ B1,
    const __half* __restrict__ B2,
    void* __restrict__ O0, void* __restrict__ O1, void* __restrict__ O2,
    int mode0, int mode1, int mode2,
    const float* __restrict__ sv0, const float* __restrict__ sv1,
    const float* __restrict__ cosT, const float* __restrict__ sinT,
    float ps0, float ps1,
    int K, int n0, int n1, int N0, int N1, int N2)
{
    extern __shared__ char smem[];
    const uint32_t sbase = smem_u32(smem);

    const int tid = threadIdx.x;
    const int lane = tid & 31, wid = tid >> 5;   // 0..3
    const int wm = wid >> 1, wn = wid & 1;
    const int bx = blockIdx.x;
    int mode, bn, N;
    const __half* B;
    void* O;
    const float* scaleV;
    float prescale;
    if (bx < n0) {
        mode = mode0; bn = bx * 128; B = B0; N = N0; O = O0;
        scaleV = sv0; prescale = ps0;
    } else if (bx < n0 + n1) {
        mode = mode1; bn = (bx - n0) * 128; B = B1; N = N1; O = O1;
        scaleV = sv1; prescale = ps1;
    } else {
        mode = mode2; bn = (bx - n0 - n1) * 128; B = B2; N = N2; O = O2;
        scaleV = sv0; prescale = 1.f;
    }
    const int bm = blockIdx.y * 64;
    const int NT = K / 64;

    float acc[2][8][4];
#pragma unroll
    for (int i = 0; i < 2; i++)
#pragma unroll
        for (int j = 0; j < 8; j++)
#pragma unroll
            for (int l = 0; l < 4; l++) acc[i][j][l] = 0.f;

    auto issue = [&](int it) {
        const int k0 = it * 64;
        const uint32_t sb = sbase + (it % 3) * G_STAGE;
#pragma unroll
        for (int i = 0; i < 12; i++) {
            int id = i * 128 + tid;          // 0..1535
            if (id < 512) {                  // A: 64 rows x 8 chunks
                int r = id >> 3, c = id & 7;
                CP16(sb + SWZG(r, c), Ahp + (size_t)(bm + r) * K + k0 + c * 8);
            } else {                         // B: 128 rows x 8 chunks
                int idb = id - 512;
                int r = idb >> 3, c = idb & 7;
                CP16(sb + 8192 + SWZG(r, c), B + (size_t)(bn + r) * K + k0 + c * 8);
            }
        }
    };

    issue(0); CP_COMMIT();
    issue(1); CP_COMMIT();

    const int lrow = lane & 15, lc = lane >> 4;

    for (int it = 0; it < NT; ++it) {
        if (it + 1 < NT) { CP_WAIT(1); } else { CP_WAIT(0); }
        __syncthreads();
        if (it + 2 < NT) { issue(it + 2); CP_COMMIT(); }

        const uint32_t sb = sbase + (it % 3) * G_STAGE;
#pragma unroll
        for (int ks = 0; ks < 4; ks++) {
            const int c = ks * 2 + lc;
            uint32_t ah[2][4];
#pragma unroll
            for (int mt = 0; mt < 2; mt++) {
                int r = wm * 32 + mt * 16 + lrow;
                LDSM_X4(ah[mt][0], ah[mt][1], ah[mt][2], ah[mt][3], sb + SWZG(r, c));
            }
#pragma unroll
            for (int j = 0; j < 4; j++) {
                int r = wn * 64 + 16 * j + lrow;
                uint32_t b4[4];
                LDSM_X4(b4[0], b4[1], b4[2], b4[3], sb + 8192 + SWZG(r, c));
#pragma unroll
                for (int half = 0; half < 2; half++) {
                    int nt = 2 * j + half;
#pragma unroll
                    for (int mt = 0; mt < 2; mt++)
                        mma_h(acc[mt][nt], ah[mt], b4[half], b4[half + 2]);
                }
            }
        }
        // no bottom barrier: 3-stage rotation + next top barrier order reuse
    }

    // ---- epilogue ----
    const int g = lane >> 2, q = lane & 3;
    if (mode == 0) {
        float* Cf = (float*)O;
#pragma unroll
        for (int mt = 0; mt < 2; mt++)
#pragma unroll
            for (int nt = 0; nt < 8; nt++) {
                int row = bm + wm * 32 + mt * 16 + g;
                int col = bn + wn * 64 + nt * 8 + 2 * q;
                *(float2*)&Cf[(size_t)row * N + col] =
                    make_float2(acc[mt][nt][0], acc[mt][nt][1]);
                *(float2*)&Cf[(size_t)(row + 8) * N + col] =
                    make_float2(acc[mt][nt][2], acc[mt][nt][3]);
            }
    } else if (mode == 1) {
        uint32_t* Ch = (uint32_t*)O;
#pragma unroll
        for (int mt = 0; mt < 2; mt++)
#pragma unroll
            for (int nt = 0; nt < 8; nt++) {
                int row = bm + wm * 32 + mt * 16 + g;
                int col = bn + wn * 64 + nt * 8 + 2 * q;
                Ch[((size_t)row * N + col) >> 1] =
                    pack_h2(acc[mt][nt][0], acc[mt][nt][1]);
                Ch[((size_t)(row + 8) * N + col) >> 1] =
                    pack_h2(acc[mt][nt][2], acc[mt][nt][3]);
            }
    } else {
        // fused RMSNorm (this block's 128 cols = one head) + RoPE -> fp16
        float* red = (float*)(smem + 3 * G_STAGE);  // [2 wn][64 rows]
        __syncthreads();
#pragma unroll
        for (int mt = 0; mt < 2; mt++) {
            float s0 = 0.f, s1 = 0.f;
#pragma unroll
            for (int nt = 0; nt < 8; nt++) {
                s0 += acc[mt][nt][0] * acc[mt][nt][0] + acc[mt][nt][1] * acc[mt][nt][1];
                s1 += acc[mt][nt][2] * acc[mt][nt][2] + acc[mt][nt][3] * acc[mt][nt][3];
            }
            s0 += __shfl_xor_sync(0xffffffffu, s0, 1);
            s0 += __shfl_xor_sync(0xffffffffu, s0, 2);
            s1 += __shfl_xor_sync(0xffffffffu, s1, 1);
            s1 += __shfl_xor_sync(0xffffffffu, s1, 2);
            if (q == 0) {
                red[wn * 64 + wm * 32 + mt * 16 + g] = s0;
                red[wn * 64 + wm * 32 + mt * 16 + g + 8] = s1;
            }
        }
        __syncthreads();
        uint32_t* Ch = (uint32_t*)O;
#pragma unroll
        for (int mt = 0; mt < 2; mt++) {
#pragma unroll
            for (int rr = 0; rr < 2; rr++) {
                int r = wm * 32 + mt * 16 + g + rr * 8;
                float rinv = rsqrtf((red[r] + red[64 + r]) * (1.0f / HD) + EPS);
                int t = (bm + r) & (T_LEN - 1);
#pragma unroll
                for (int nt = 0; nt < 8; nt++) {
                    int d = wn * 64 + nt * 8 + 2 * q;
                    float2 sc = *(const float2*)&scaleV[d];
                    float2 cs = *(const float2*)&cosT[t * HD + d];
                    float2 sn = *(const float2*)&sinT[t * HD + d];
                    float v0 = acc[mt][nt][rr * 2 + 0] * rinv * sc.x;
                    float v1 = acc[mt][nt][rr * 2 + 1] * rinv * sc.y;
                    float o0 = (v0 * cs.x - v1 * sn.x) * prescale;
                    float o1 = (v1 * cs.y + v0 * sn.y) * prescale;
                    Ch[(((size_t)(bm + r)) * N + bn + d) >> 1] = pack_h2(o0, o1);
                }
            }
        }
    }
}

// ---------------- FP16 HMMA causal GQA flash attention (R13 config) -----------
// BQ=64 (4 warps x m16), BK=64, HD=128. Q persistent (16KB) +
// 3-stage K/V (3 x 32KB) = 112KB -> 2 CTAs/SM. 128 threads.
#define FA_KV_STAGE 32768
#define FA_SMEM (16384 + 3 * FA_KV_STAGE)
#define SWZ256(r, c) ((uint32_t)((r) * 256 + (((c) ^ ((r) & 7)) << 4)))

__global__ __launch_bounds__(128) void flash_mma(
    const __half* __restrict__ qh, const __half* __restrict__ kh,
    const __half* __restrict__ vh, __half* __restrict__ ohp)
{
    extern __shared__ char fsm[];
    const uint32_t sb = smem_u32(fsm);
    const uint32_t Qh_s = sb;
    const uint32_t ST = sb + 16384;  // per stage: Kh(16K) Vh(16K)

    const int qb = (int)gridDim.x - 1 - (int)blockIdx.x;  // heavy tiles first
    const int h = blockIdx.y, b = blockIdx.z;
    const int kvh = h >> 2;
    const int tid = threadIdx.x;
    const int lane = tid & 31, wid = tid >> 5;   // wid 0..3
    const int g = lane >> 2, qq = lane & 3;
    const int q0 = qb * 64;
    const int q0w = q0 + wid * 16;
    const int nkv = qb + 1;

#pragma unroll
    for (int i = 0; i < 8; i++) {
        int id = i * 128 + tid;
        int c = id & 15, r = id >> 4;
        CP16(Qh_s + SWZ256(r, c),
             qh + ((size_t)(b * T_LEN + q0 + r) * NH + h) * HD + c * 8);
    }
    CP_COMMIT();

    auto issue_kv = [&](int kt) {
        const int kv0 = kt * 64;
        const uint32_t sbs = ST + (kt % 3) * FA_KV_STAGE;
#pragma unroll
        for (int i = 0; i < 16; i++) {
            int id = i * 128 + tid;
            int c = id & 15, r = (id >> 4) & 63, arr = id >> 10;  // k, v
            const __half* src = arr ? vh : kh;
            uint32_t dst = sbs + arr * 16384 + SWZ256(r, c);
            CP16(dst, src + ((size_t)(b * T_LEN + kv0 + r) * NKV + kvh) * HD + c * 8);
        }
    };

    issue_kv(0);
    CP_COMMIT();
    if (nkv > 1) { issue_kv(1); CP_COMMIT(); }

    float m0 = -1e30f, m1 = -1e30f, l0 = 0.f, l1 = 0.f;
    float Oacc[16][4];
#pragma unroll
    for (int nt = 0; nt < 16; nt++)
#pragma unroll
        for (int e = 0; e < 4; e++) Oacc[nt][e] = 0.f;

    const int lrow = lane & 15, lc = lane >> 4;

    for (int kt = 0; kt < nkv; kt++) {
        if (kt + 1 < nkv) { CP_WAIT(1); } else { CP_WAIT(0); }
        __syncthreads();
        if (kt + 2 < nkv) { issue_kv(kt + 2); CP_COMMIT(); }

        const int kv0 = kt * 64;
        const uint32_t sbs = ST + (kt % 3) * FA_KV_STAGE;

        {
            float S[8][4];
#pragma unroll
            for (int nt = 0; nt < 8; nt++)
#pragma unroll
                for (int e = 0; e < 4; e++) S[nt][e] = 0.f;

#pragma unroll
            for (int ks = 0; ks < 8; ks++) {
                const int c = ks * 2 + lc;
                int qr = wid * 16 + lrow;
                uint32_t aq[4];
                LDSM_X4(aq[0], aq[1], aq[2], aq[3], Qh_s + SWZ256(qr, c));
#pragma unroll
                for (int j = 0; j < 4; j++) {
                    int r = 16 * j + lrow;
                    uint32_t b4[4];
                    LDSM_X4(b4[0], b4[1], b4[2], b4[3], sbs + SWZ256(r, c));
#pragma unroll
                    for (int half = 0; half < 2; half++)
                        mma_h(S[2 * j + half], aq, b4[half], b4[half + 2]);
                }
            }

            if (kv0 + 63 > q0w) {  // diagonal region: mask
#pragma unroll
                for (int nt = 0; nt < 8; nt++) {
                    int col = kv0 + nt * 8 + qq * 2;
                    int r0 = q0w + g, r1 = q0w + g + 8;
                    if (col > r0) S[nt][0] = -1e30f;
                    if (col + 1 > r0) S[nt][1] = -1e30f;
                    if (col > r1) S[nt][2] = -1e30f;
                    if (col + 1 > r1) S[nt][3] = -1e30f;
                }
            }

            float mx0 = -1e30f, mx1 = -1e30f;
#pragma unroll
            for (int nt = 0; nt < 8; nt++) {
                mx0 = fmaxf(mx0, fmaxf(S[nt][0], S[nt][1]));
                mx1 = fmaxf(mx1, fmaxf(S[nt][2], S[nt][3]));
            }
            mx0 = fmaxf(mx0, __shfl_xor_sync(0xffffffffu, mx0, 1));
            mx0 = fmaxf(mx0, __shfl_xor_sync(0xffffffffu, mx0, 2));
            mx1 = fmaxf(mx1, __shfl_xor_sync(0xffffffffu, mx1, 1));
            mx1 = fmaxf(mx1, __shfl_xor_sync(0xffffffffu, mx1, 2));
            float mn0 = fmaxf(m0, mx0), mn1 = fmaxf(m1, mx1);
            float al0 = exp2f(m0 - mn0), al1 = exp2f(m1 - mn1);
            m0 = mn0; m1 = mn1;
            float sum0 = 0.f, sum1 = 0.f;
#pragma unroll
            for (int nt = 0; nt < 8; nt++) {
                S[nt][0] = exp2f(S[nt][0] - mn0);
                S[nt][1] = exp2f(S[nt][1] - mn0);
                S[nt][2] = exp2f(S[nt][2] - mn1);
                S[nt][3] = exp2f(S[nt][3] - mn1);
                sum0 += S[nt][0] + S[nt][1];
                sum1 += S[nt][2] + S[nt][3];
            }
            sum0 += __shfl_xor_sync(0xffffffffu, sum0, 1);
            sum0 += __shfl_xor_sync(0xffffffffu, sum0, 2);
            sum1 += __shfl_xor_sync(0xffffffffu, sum1, 1);
            sum1 += __shfl_xor_sync(0xffffffffu, sum1, 2);
            l0 = l0 * al0 + sum0;
            l1 = l1 * al1 + sum1;
#pragma unroll
            for (int nt = 0; nt < 16; nt++) {
                Oacc[nt][0] *= al0; Oacc[nt][1] *= al0;
                Oacc[nt][2] *= al1; Oacc[nt][3] *= al1;
            }

            uint32_t Ph[4][4];
#pragma unroll
            for (int ktp = 0; ktp < 4; ktp++) {
                Ph[ktp][0] = pack_h2(S[2 * ktp][0], S[2 * ktp][1]);
                Ph[ktp][1] = pack_h2(S[2 * ktp][2], S[2 * ktp][3]);
                Ph[ktp][2] = pack_h2(S[2 * ktp + 1][0], S[2 * ktp + 1][1]);
                Ph[ktp][3] = pack_h2(S[2 * ktp + 1][2], S[2 * ktp + 1][3]);
            }

#pragma unroll
            for (int ktp = 0; ktp < 4; ktp++) {
#pragma unroll
                for (int j = 0; j < 8; j++) {
                    int r = ktp * 16 + lrow;
                    int c = 2 * j + lc;
                    uint32_t v0, v1, v2, v3;
                    LDSM_X4_T(v0, v1, v2, v3, sbs + 16384 + SWZ256(r, c));
                    mma_h(Oacc[2 * j], Ph[ktp], v0, v1);
                    mma_h(Oacc[2 * j + 1], Ph[ktp], v2, v3);
                }
            }
        }
        // no bottom barrier: 3-stage rotation + next top barrier order reuse
    }

    // ---- write O as fp16 (att layout [b*T, NH*HD]) ----
    float inv0 = 1.f / l0, inv1 = 1.f / l1;
    const size_t base0 = (size_t)(b * T_LEN + q0w + g) * (NH * HD) + h * HD;
    const size_t base1 = base0 + (size_t)8 * NH * HD;
#pragma unroll
    for (int nt = 0; nt < 16; nt++) {
        int col = nt * 8 + qq * 2;
        ((uint32_t*)ohp)[(base0 + col) >> 1] =
            pack_h2(Oacc[nt][0] * inv0, Oacc[nt][1] * inv0);
        ((uint32_t*)ohp)[(base1 + col) >> 1] =
            pack_h2(Oacc[nt][2] * inv1, Oacc[nt][3] * inv1);
    }
}

// ---------------- launcher ---------------------------------------------------
extern "C" void kernel_launch(void* const* d_in, const int* in_sizes, int n_in,
                              void* d_out, int out_size)
{
    const float* x       = (const float*)d_in[0];
    const float* Wq      = (const float*)d_in[1];
    const float* Wk      = (const float*)d_in[2];
    const float* Wv      = (const float*)d_in[3];
    const float* Wo      = (const float*)d_in[4];
    const float* q_scale = (const float*)d_in[5];
    const float* k_scale = (const float*)d_in[6];
    const float* cosT    = (const float*)d_in[7];
    const float* sinT    = (const float*)d_in[8];
    float* out = (float*)d_out;

    __half *xh, *ah, *wq, *wk, *wv, *wo, *qh, *kh, *vh;
    cudaGetSymbolAddress((void**)&xh, g_xh);
    cudaGetSymbolAddress((void**)&ah, g_ah);
    cudaGetSymbolAddress((void**)&wq, g_wq);  cudaGetSymbolAddress((void**)&wk, g_wk);
    cudaGetSymbolAddress((void**)&wv, g_wv);  cudaGetSymbolAddress((void**)&wo, g_wo);
    cudaGetSymbolAddress((void**)&qh, g_qh);
    cudaGetSymbolAddress((void**)&kh, g_kh);  cudaGetSymbolAddress((void**)&vh, g_vh);

    static bool attr_set = false;
    if (!attr_set) {
        cudaFuncSetAttribute(mma_gemm, cudaFuncAttributeMaxDynamicSharedMemorySize, GEMM_SMEM);
        cudaFuncSetAttribute(flash_mma, cudaFuncAttributeMaxDynamicSharedMemorySize, FA_SMEM);
        attr_set = true;
    }

    const int M = M_ROWS;  // 4096
    const float qk_scale = 1.4426950408889634f * 0.08838834764831845f;  // log2e/sqrt(HD)

    // one merged conversion launch
    prep<<<18432, 256>>>(x, Wq, Wk, Wv, Wo, xh, wq, wk, wv, wo);

    // merged Q+K+V projections with fused RMSNorm+RoPE epilogues (M-tile 64)
    mma_gemm<<<dim3(24, M / 64), 128, GEMM_SMEM>>>(
        xh, wq, wk, wv, qh, kh, vh,
        2, 2, 1,
        q_scale, k_scale, cosT, sinT,
        qk_scale, 1.0f,
        D_MODEL, 16, 4, NH * HD, NKV * HD, NKV * HD);

    // flash attention -> fp16 (R13 config: BQ=64, 3-stage KV, 2 CTAs/SM)
    flash_mma<<<dim3(T_LEN / 64, NH, BATCH), 128, FA_SMEM>>>(qh, kh, vh, ah);

    // output projection (fp32 out, M-tile 64)
    mma_gemm<<<dim3(16, M / 64), 128, GEMM_SMEM>>>(
        ah, wo, nullptr, nullptr, out, nullptr, nullptr,
        0, 0, 0,
        nullptr, nullptr, nullptr, nullptr,
        1.0f, 1.0f,
        D_MODEL, 16, 0, D_MODEL, 0, 0);
}